// round 3
// baseline (speedup 1.0000x reference)
#include <cuda_runtime.h>
#include <math.h>

// Problem dims
#define T_STEPS 512
#define B 256
#define D 256
#define H 512
#define G4 2048        // 4*H (LSTM gates)
#define ZW 3584        // 3*H (gi) + 3*H (gh) + H (h3)
#define NBLK 128       // persistent grid: (B/32) * (H/32) = 8*16

// ---------------- device scratch (no allocation allowed) ----------------
__device__ float g_Xproj[(size_t)T_STEPS * B * G4]; // per-step input projection + biases
__device__ float g_Whc[G4 * H];                     // Wih[:,D:] + Whh   [j][k]
__device__ float g_M[H * H];                        // phase @ fe_W^T    [k][j]
__device__ float g_Wbig[H * ZW];                    // [k][j]: [M@Wih_g^T | M@Whh_g^T | M]
__device__ float g_bbig[ZW];
__device__ float g_hx[B * H];
__device__ float g_cx[B * H];
__device__ float g_h1[B * H];

// grid-barrier state (persists across graph replays; gen is re-read at entry)
__device__ unsigned g_count = 0;
__device__ volatile unsigned g_sense = 0;

__device__ __forceinline__ float sigmoidf_(float x) {
    return 1.0f / (1.0f + expf(-x));
}

// ---------------- init ----------------
__global__ void k_init() {
    int i = blockIdx.x * blockDim.x + threadIdx.x;
    if (i < B * H) { g_hx[i] = 0.0f; g_cx[i] = 0.0f; }
}

// ---------------- Whc = Wih[:, D:] + Whh ----------------
__global__ void k_whc(const float* __restrict__ Wih, const float* __restrict__ Whh) {
    int idx = blockIdx.x * blockDim.x + threadIdx.x;
    if (idx < G4 * H) {
        int j = idx >> 9;
        int k = idx & 511;
        g_Whc[idx] = Wih[(size_t)j * (D + H) + D + k] + Whh[idx];
    }
}

// ---------------- generic NT GEMM (precompute only) ----------------
__global__ __launch_bounds__(256) void gemm_nt(
    const float* __restrict__ A, const float* __restrict__ Bm, float* __restrict__ C,
    const float* __restrict__ bias1, const float* __restrict__ bias2,
    int K, int lda, int ldb, int ldc, int coloff)
{
    __shared__ float sA[32][33];
    __shared__ float sB[32][33];
    int t = threadIdx.x;
    int i0 = blockIdx.x * 32, j0 = blockIdx.y * 32;
    int tx = t & 15, ty = t >> 4;
    float a00 = 0.f, a01 = 0.f, a10 = 0.f, a11 = 0.f;
    for (int l0 = 0; l0 < K; l0 += 32) {
        #pragma unroll
        for (int i = 0; i < 4; i++) {
            int e = t + i * 256; int r = e >> 5, cc = e & 31;
            sA[r][cc] = A[(size_t)(i0 + r) * lda + l0 + cc];
            sB[r][cc] = Bm[(size_t)(j0 + r) * ldb + l0 + cc];
        }
        __syncthreads();
        #pragma unroll
        for (int ll = 0; ll < 32; ll++) {
            float x0 = sA[ty * 2][ll],     x1 = sA[ty * 2 + 1][ll];
            float y0 = sB[tx * 2][ll],     y1 = sB[tx * 2 + 1][ll];
            a00 += x0 * y0; a01 += x0 * y1; a10 += x1 * y0; a11 += x1 * y1;
        }
        __syncthreads();
    }
    int iR = i0 + ty * 2;
    int jC = j0 + tx * 2;
    float acc[2][2] = {{a00, a01}, {a10, a11}};
    #pragma unroll
    for (int r = 0; r < 2; r++) {
        #pragma unroll
        for (int c = 0; c < 2; c++) {
            float v = acc[r][c];
            int j = jC + c;
            if (bias1) v += bias1[j];
            if (bias2) v += bias2[j];
            C[(size_t)(iR + r) * ldc + coloff + j] = v;
        }
    }
}

// ---------------- copy M into Wbig block 6 ----------------
__global__ void k_copyM() {
    int idx = blockIdx.x * blockDim.x + threadIdx.x;
    if (idx < H * H) {
        int k = idx >> 9, j = idx & 511;
        g_Wbig[(size_t)k * ZW + 3072 + j] = g_M[idx];
    }
}

// ---------------- fused bias ----------------
__global__ void k_bbig(const float* __restrict__ feb,
                       const float* __restrict__ gWih, const float* __restrict__ gWhh,
                       const float* __restrict__ gbih, const float* __restrict__ gbhh) {
    int j = blockIdx.x * blockDim.x + threadIdx.x;
    if (j >= ZW) return;
    float s;
    if (j < 1536) {
        const float* w = gWih + (size_t)j * H;
        s = gbih[j];
        for (int k = 0; k < H; k++) s += feb[k] * w[k];
    } else if (j < 3072) {
        int jj = j - 1536;
        const float* w = gWhh + (size_t)jj * H;
        s = gbhh[jj];
        for (int k = 0; k < H; k++) s += feb[k] * w[k];
    } else {
        s = feb[j - 3072];
    }
    g_bbig[j] = s;
}

// ---------------- software grid barrier (all NBLK blocks resident) ----------------
__device__ __forceinline__ void grid_barrier(unsigned& gen) {
    __syncthreads();
    if (threadIdx.x == 0) {
        __threadfence();  // publish this block's global writes
        if (atomicAdd(&g_count, 1u) == NBLK - 1) {
            g_count = 0;
            __threadfence();
            g_sense = gen + 1;  // release
        } else {
            while (g_sense == gen) { }
            __threadfence();
        }
        gen = gen + 1;
    }
    __syncthreads();
}

// ---------------- persistent recurrence kernel: all 512 steps ----------------
// grid = 128 blocks x 256 threads, all co-resident.
// Block (bq, jq): bq = bid & 7 -> batch rows b0..b0+31; jq = bid >> 3 -> cols j0..j0+31.
__global__ __launch_bounds__(256) void k_recur(float* __restrict__ out) {
    __shared__ float sHT[32][36];       // hidden tile, k-major: sHT[k][row]
    __shared__ float sW[7][32][36];     // weight tiles (stage1: [blk][col][k], stage2: [blk][k][col])

    int tid = threadIdx.x;
    int bid = blockIdx.x;
    int b0 = (bid & 7) * 32;
    int j0 = (bid >> 3) * 32;
    int c   = tid & 31;           // output column within tile
    int rg  = tid >> 5;           // row group: rows rg*4 .. rg*4+3
    int kk4 = (tid & 7) * 4;      // float4 k-offset for loads
    int r8  = tid >> 3;           // 0..31: row/col index for loads
    int h   = j0 + c;

    unsigned gen = 0;
    if (tid == 0) gen = g_sense;  // survive graph replays

    for (int t = 0; t < T_STEPS; t++) {
        float acc[7][4];

        // ================= stage 1: LSTM gates =================
        #pragma unroll
        for (int blk = 0; blk < 4; blk++)
            #pragma unroll
            for (int i = 0; i < 4; i++) acc[blk][i] = 0.f;

        for (int k0 = 0; k0 < H; k0 += 32) {
            // hx tile (cross-block producer -> bypass L1), store transposed
            {
                float4 v = __ldcg(reinterpret_cast<const float4*>(
                    &g_hx[(b0 + r8) * H + k0 + kk4]));
                sHT[kk4 + 0][r8] = v.x;
                sHT[kk4 + 1][r8] = v.y;
                sHT[kk4 + 2][r8] = v.z;
                sHT[kk4 + 3][r8] = v.w;
            }
            // Whc tiles: sW[blk][col][k]
            #pragma unroll
            for (int blk = 0; blk < 4; blk++) {
                float4 w = *reinterpret_cast<const float4*>(
                    &g_Whc[(size_t)(blk * H + j0 + r8) * H + k0 + kk4]);
                *reinterpret_cast<float4*>(&sW[blk][r8][kk4]) = w;
            }
            __syncthreads();
            #pragma unroll
            for (int kk = 0; kk < 32; kk++) {
                float4 x = *reinterpret_cast<const float4*>(&sHT[kk][rg * 4]);
                #pragma unroll
                for (int blk = 0; blk < 4; blk++) {
                    float w = sW[blk][c][kk];
                    acc[blk][0] += x.x * w;
                    acc[blk][1] += x.y * w;
                    acc[blk][2] += x.z * w;
                    acc[blk][3] += x.w * w;
                }
            }
            __syncthreads();
        }
        #pragma unroll
        for (int i = 0; i < 4; i++) {
            int b = b0 + rg * 4 + i;
            size_t xb = ((size_t)t * B + b) * G4;
            float gi = acc[0][i] + __ldcs(&g_Xproj[xb + 0 * H + h]);
            float gf = acc[1][i] + __ldcs(&g_Xproj[xb + 1 * H + h]);
            float gg = acc[2][i] + __ldcs(&g_Xproj[xb + 2 * H + h]);
            float go = acc[3][i] + __ldcs(&g_Xproj[xb + 3 * H + h]);
            float iv = sigmoidf_(gi);
            float fv = sigmoidf_(gf);
            float gv = tanhf(gg);
            float ov = sigmoidf_(go);
            float cp = g_cx[b * H + h];          // same thread wrote it last step
            float cn = fv * cp + iv * gv;
            g_cx[b * H + h] = cn;
            __stcg(&g_h1[b * H + h], ov * tanhf(cn));
        }

        grid_barrier(gen);

        // ================= stage 2: phase/fe folded GRU =================
        #pragma unroll
        for (int blk = 0; blk < 7; blk++)
            #pragma unroll
            for (int i = 0; i < 4; i++) acc[blk][i] = 0.f;

        for (int k0 = 0; k0 < H; k0 += 32) {
            {
                float4 v = __ldcg(reinterpret_cast<const float4*>(
                    &g_h1[(b0 + r8) * H + k0 + kk4]));
                sHT[kk4 + 0][r8] = v.x;
                sHT[kk4 + 1][r8] = v.y;
                sHT[kk4 + 2][r8] = v.z;
                sHT[kk4 + 3][r8] = v.w;
            }
            // Wbig tiles: sW[blk][k][col]
            #pragma unroll
            for (int blk = 0; blk < 7; blk++) {
                float4 w = *reinterpret_cast<const float4*>(
                    &g_Wbig[(size_t)(k0 + r8) * ZW + blk * H + j0 + kk4]);
                *reinterpret_cast<float4*>(&sW[blk][r8][kk4]) = w;
            }
            __syncthreads();
            #pragma unroll
            for (int kk = 0; kk < 32; kk++) {
                float4 x = *reinterpret_cast<const float4*>(&sHT[kk][rg * 4]);
                #pragma unroll
                for (int blk = 0; blk < 7; blk++) {
                    float w = sW[blk][kk][c];
                    acc[blk][0] += x.x * w;
                    acc[blk][1] += x.y * w;
                    acc[blk][2] += x.z * w;
                    acc[blk][3] += x.w * w;
                }
            }
            __syncthreads();
        }
        #pragma unroll
        for (int i = 0; i < 4; i++) {
            int b = b0 + rg * 4 + i;
            float ir  = acc[0][i] + g_bbig[0 * H + h];
            float iz  = acc[1][i] + g_bbig[1 * H + h];
            float inn = acc[2][i] + g_bbig[2 * H + h];
            float hr  = acc[3][i] + g_bbig[3 * H + h];
            float hz  = acc[4][i] + g_bbig[4 * H + h];
            float hn  = acc[5][i] + g_bbig[5 * H + h];
            float h3  = acc[6][i] + g_bbig[6 * H + h];
            float r = sigmoidf_(ir + hr);
            float z = sigmoidf_(iz + hz);
            float n = tanhf(inn + r * hn);
            float hnew = (1.0f - z) * n + z * h3;
            __stcs(&out[((size_t)t * B + b) * H + h], hnew);
            __stcg(&g_hx[b * H + h], hnew);
        }

        grid_barrier(gen);
    }
}

// ---------------- finalize: append hx, cx after outputs ----------------
__global__ void k_finalize(float* __restrict__ out) {
    int i = blockIdx.x * blockDim.x + threadIdx.x;
    if (i < B * H) {
        out[(size_t)T_STEPS * B * H + i] = g_hx[i];
        out[(size_t)T_STEPS * B * H + B * H + i] = g_cx[i];
    }
}

// ---------------- host ----------------
extern "C" void kernel_launch(void* const* d_in, const int* in_sizes, int n_in,
                              void* d_out, int out_size) {
    (void)in_sizes; (void)n_in; (void)out_size;
    const float* inputs   = (const float*)d_in[0];
    const float* lstm_Wih = (const float*)d_in[1];
    const float* lstm_Whh = (const float*)d_in[2];
    const float* lstm_bih = (const float*)d_in[3];
    const float* lstm_bhh = (const float*)d_in[4];
    const float* phase    = (const float*)d_in[5];
    const float* fe_W     = (const float*)d_in[6];
    const float* fe_b     = (const float*)d_in[7];
    const float* gru_Wih  = (const float*)d_in[8];
    const float* gru_Whh  = (const float*)d_in[9];
    const float* gru_bih  = (const float*)d_in[10];
    const float* gru_bhh  = (const float*)d_in[11];
    float* out = (float*)d_out;

    float *pM, *pWbig, *pXproj;
    cudaGetSymbolAddress((void**)&pM, g_M);
    cudaGetSymbolAddress((void**)&pWbig, g_Wbig);
    cudaGetSymbolAddress((void**)&pXproj, g_Xproj);

    // state init (graph replays must be deterministic)
    k_init<<<(B * H + 255) / 256, 256>>>();

    // precompute folded weights
    k_whc<<<(G4 * H + 255) / 256, 256>>>(lstm_Wih, lstm_Whh);

    // M = phase @ fe_W^T
    gemm_nt<<<dim3(H / 32, H / 32), 256>>>(phase, fe_W, pM, nullptr, nullptr,
                                           H, H, H, H, 0);
    // Wbig[:, 0:1536] = M @ gru_Wih^T
    gemm_nt<<<dim3(H / 32, 1536 / 32), 256>>>(pM, gru_Wih, pWbig, nullptr, nullptr,
                                              H, H, H, ZW, 0);
    // Wbig[:, 1536:3072] = M @ gru_Whh^T
    gemm_nt<<<dim3(H / 32, 1536 / 32), 256>>>(pM, gru_Whh, pWbig, nullptr, nullptr,
                                              H, H, H, ZW, 1536);
    // Wbig[:, 3072:3584] = M
    k_copyM<<<(H * H + 255) / 256, 256>>>();

    // fused GRU-side bias
    k_bbig<<<(ZW + 255) / 256, 256>>>(fe_b, gru_Wih, gru_Whh, gru_bih, gru_bhh);

    // Xproj[t,b,:] = x @ Wih[:, :D]^T + bih + bhh  (big parallel GEMM)
    gemm_nt<<<dim3((T_STEPS * B) / 32, G4 / 32), 256>>>(
        inputs, lstm_Wih, pXproj, lstm_bih, lstm_bhh,
        D, D, D + H, G4, 0);

    // ONE persistent kernel for the whole recurrence (keeps graph tiny)
    k_recur<<<NBLK, 256>>>(out);

    k_finalize<<<(B * H + 255) / 256, 256>>>(out);
}

// round 4
// speedup vs baseline: 1.0467x; 1.0467x over previous
#include <cuda_runtime.h>
#include <math.h>

// Problem dims
#define T_STEPS 512
#define B 256
#define D 256
#define H 512
#define G4 2048        // 4*H (LSTM gates)
#define ZW 3584        // 3*H (gi) + 3*H (gh) + H (h3)
#define NBLK 128       // persistent grid: (B/32) * (H/32) = 8*16

// ---------------- device scratch (no allocation allowed) ----------------
__device__ float g_Xproj[(size_t)T_STEPS * B * G4]; // per-step input projection + biases
__device__ float g_Whc[G4 * H];                     // Wih[:,D:] + Whh   [j][k]
__device__ float g_M[H * H];                        // phase @ fe_W^T    [k][j]
__device__ float g_Wbig[H * ZW];                    // [k][j]: [M@Wih_g^T | M@Whh_g^T | M]
__device__ float g_bbig[ZW];
__device__ float g_hx[B * H];
__device__ float g_cx[B * H];
__device__ float g_h1[B * H];

// grid-barrier state (persists across graph replays; gen is re-read at entry)
__device__ unsigned g_count = 0;
__device__ volatile unsigned g_sense = 0;

__device__ __forceinline__ float sigmoidf_(float x) {
    return 1.0f / (1.0f + expf(-x));
}

// ---------------- init ----------------
__global__ void k_init() {
    int i = blockIdx.x * blockDim.x + threadIdx.x;
    if (i < B * H) { g_hx[i] = 0.0f; g_cx[i] = 0.0f; }
}

// ---------------- Whc = Wih[:, D:] + Whh ----------------
__global__ void k_whc(const float* __restrict__ Wih, const float* __restrict__ Whh) {
    int idx = blockIdx.x * blockDim.x + threadIdx.x;
    if (idx < G4 * H) {
        int j = idx >> 9;
        int k = idx & 511;
        g_Whc[idx] = Wih[(size_t)j * (D + H) + D + k] + Whh[idx];
    }
}

// ---------------- generic NT GEMM (precompute only) ----------------
__global__ __launch_bounds__(256) void gemm_nt(
    const float* __restrict__ A, const float* __restrict__ Bm, float* __restrict__ C,
    const float* __restrict__ bias1, const float* __restrict__ bias2,
    int K, int lda, int ldb, int ldc, int coloff)
{
    __shared__ float sA[32][33];
    __shared__ float sB[32][33];
    int t = threadIdx.x;
    int i0 = blockIdx.x * 32, j0 = blockIdx.y * 32;
    int tx = t & 15, ty = t >> 4;
    float a00 = 0.f, a01 = 0.f, a10 = 0.f, a11 = 0.f;
    for (int l0 = 0; l0 < K; l0 += 32) {
        #pragma unroll
        for (int i = 0; i < 4; i++) {
            int e = t + i * 256; int r = e >> 5, cc = e & 31;
            sA[r][cc] = A[(size_t)(i0 + r) * lda + l0 + cc];
            sB[r][cc] = Bm[(size_t)(j0 + r) * ldb + l0 + cc];
        }
        __syncthreads();
        #pragma unroll
        for (int ll = 0; ll < 32; ll++) {
            float x0 = sA[ty * 2][ll],     x1 = sA[ty * 2 + 1][ll];
            float y0 = sB[tx * 2][ll],     y1 = sB[tx * 2 + 1][ll];
            a00 += x0 * y0; a01 += x0 * y1; a10 += x1 * y0; a11 += x1 * y1;
        }
        __syncthreads();
    }
    int iR = i0 + ty * 2;
    int jC = j0 + tx * 2;
    float acc[2][2] = {{a00, a01}, {a10, a11}};
    #pragma unroll
    for (int r = 0; r < 2; r++) {
        #pragma unroll
        for (int c = 0; c < 2; c++) {
            float v = acc[r][c];
            int j = jC + c;
            if (bias1) v += bias1[j];
            if (bias2) v += bias2[j];
            C[(size_t)(iR + r) * ldc + coloff + j] = v;
        }
    }
}

// ---------------- copy M into Wbig block 6 ----------------
__global__ void k_copyM() {
    int idx = blockIdx.x * blockDim.x + threadIdx.x;
    if (idx < H * H) {
        int k = idx >> 9, j = idx & 511;
        g_Wbig[(size_t)k * ZW + 3072 + j] = g_M[idx];
    }
}

// ---------------- fused bias ----------------
__global__ void k_bbig(const float* __restrict__ feb,
                       const float* __restrict__ gWih, const float* __restrict__ gWhh,
                       const float* __restrict__ gbih, const float* __restrict__ gbhh) {
    int j = blockIdx.x * blockDim.x + threadIdx.x;
    if (j >= ZW) return;
    float s;
    if (j < 1536) {
        const float* w = gWih + (size_t)j * H;
        s = gbih[j];
        for (int k = 0; k < H; k++) s += feb[k] * w[k];
    } else if (j < 3072) {
        int jj = j - 1536;
        const float* w = gWhh + (size_t)jj * H;
        s = gbhh[jj];
        for (int k = 0; k < H; k++) s += feb[k] * w[k];
    } else {
        s = feb[j - 3072];
    }
    g_bbig[j] = s;
}

// ---------------- software grid barrier (all NBLK blocks resident) ----------------
__device__ __forceinline__ void grid_barrier(unsigned& gen) {
    __syncthreads();
    if (threadIdx.x == 0) {
        __threadfence();  // publish this block's global writes
        if (atomicAdd(&g_count, 1u) == NBLK - 1) {
            g_count = 0;
            __threadfence();
            g_sense = gen + 1;  // release
        } else {
            while (g_sense == gen) { }
            __threadfence();
        }
        gen = gen + 1;
    }
    __syncthreads();
}

// ---------------- persistent recurrence kernel: all 512 steps ----------------
// grid = 128 blocks x 256 threads, all co-resident.
// Block (bq, jq): bq = bid & 7 -> batch rows b0..b0+31; jq = bid >> 3 -> cols j0..j0+31.
__global__ __launch_bounds__(256) void k_recur(float* __restrict__ out) {
    __shared__ float sHT[32][36];       // hidden tile, k-major: sHT[k][row]
    __shared__ float sW[7][32][36];     // weight tiles (stage1: [blk][col][k], stage2: [blk][k][col])

    int tid = threadIdx.x;
    int bid = blockIdx.x;
    int b0 = (bid & 7) * 32;
    int j0 = (bid >> 3) * 32;
    int c   = tid & 31;           // output column within tile
    int rg  = tid >> 5;           // row group: rows rg*4 .. rg*4+3
    int kk4 = (tid & 7) * 4;      // float4 k-offset for loads
    int r8  = tid >> 3;           // 0..31: row/col index for loads
    int h   = j0 + c;

    unsigned gen = 0;
    if (tid == 0) gen = g_sense;  // survive graph replays

    for (int t = 0; t < T_STEPS; t++) {
        float acc[7][4];

        // ================= stage 1: LSTM gates =================
        #pragma unroll
        for (int blk = 0; blk < 4; blk++)
            #pragma unroll
            for (int i = 0; i < 4; i++) acc[blk][i] = 0.f;

        for (int k0 = 0; k0 < H; k0 += 32) {
            // hx tile (cross-block producer -> bypass L1), store transposed
            {
                float4 v = __ldcg(reinterpret_cast<const float4*>(
                    &g_hx[(b0 + r8) * H + k0 + kk4]));
                sHT[kk4 + 0][r8] = v.x;
                sHT[kk4 + 1][r8] = v.y;
                sHT[kk4 + 2][r8] = v.z;
                sHT[kk4 + 3][r8] = v.w;
            }
            // Whc tiles: sW[blk][col][k]
            #pragma unroll
            for (int blk = 0; blk < 4; blk++) {
                float4 w = *reinterpret_cast<const float4*>(
                    &g_Whc[(size_t)(blk * H + j0 + r8) * H + k0 + kk4]);
                *reinterpret_cast<float4*>(&sW[blk][r8][kk4]) = w;
            }
            __syncthreads();
            #pragma unroll
            for (int kk = 0; kk < 32; kk++) {
                float4 x = *reinterpret_cast<const float4*>(&sHT[kk][rg * 4]);
                #pragma unroll
                for (int blk = 0; blk < 4; blk++) {
                    float w = sW[blk][c][kk];
                    acc[blk][0] += x.x * w;
                    acc[blk][1] += x.y * w;
                    acc[blk][2] += x.z * w;
                    acc[blk][3] += x.w * w;
                }
            }
            __syncthreads();
        }
        #pragma unroll
        for (int i = 0; i < 4; i++) {
            int b = b0 + rg * 4 + i;
            size_t xb = ((size_t)t * B + b) * G4;
            float gi = acc[0][i] + __ldcs(&g_Xproj[xb + 0 * H + h]);
            float gf = acc[1][i] + __ldcs(&g_Xproj[xb + 1 * H + h]);
            float gg = acc[2][i] + __ldcs(&g_Xproj[xb + 2 * H + h]);
            float go = acc[3][i] + __ldcs(&g_Xproj[xb + 3 * H + h]);
            float iv = sigmoidf_(gi);
            float fv = sigmoidf_(gf);
            float gv = tanhf(gg);
            float ov = sigmoidf_(go);
            float cp = g_cx[b * H + h];          // same thread wrote it last step
            float cn = fv * cp + iv * gv;
            g_cx[b * H + h] = cn;
            __stcg(&g_h1[b * H + h], ov * tanhf(cn));
        }

        grid_barrier(gen);

        // ================= stage 2: phase/fe folded GRU =================
        #pragma unroll
        for (int blk = 0; blk < 7; blk++)
            #pragma unroll
            for (int i = 0; i < 4; i++) acc[blk][i] = 0.f;

        for (int k0 = 0; k0 < H; k0 += 32) {
            {
                float4 v = __ldcg(reinterpret_cast<const float4*>(
                    &g_h1[(b0 + r8) * H + k0 + kk4]));
                sHT[kk4 + 0][r8] = v.x;
                sHT[kk4 + 1][r8] = v.y;
                sHT[kk4 + 2][r8] = v.z;
                sHT[kk4 + 3][r8] = v.w;
            }
            // Wbig tiles: sW[blk][k][col]
            #pragma unroll
            for (int blk = 0; blk < 7; blk++) {
                float4 w = *reinterpret_cast<const float4*>(
                    &g_Wbig[(size_t)(k0 + r8) * ZW + blk * H + j0 + kk4]);
                *reinterpret_cast<float4*>(&sW[blk][r8][kk4]) = w;
            }
            __syncthreads();
            #pragma unroll
            for (int kk = 0; kk < 32; kk++) {
                float4 x = *reinterpret_cast<const float4*>(&sHT[kk][rg * 4]);
                #pragma unroll
                for (int blk = 0; blk < 7; blk++) {
                    float w = sW[blk][kk][c];
                    acc[blk][0] += x.x * w;
                    acc[blk][1] += x.y * w;
                    acc[blk][2] += x.z * w;
                    acc[blk][3] += x.w * w;
                }
            }
            __syncthreads();
        }
        #pragma unroll
        for (int i = 0; i < 4; i++) {
            int b = b0 + rg * 4 + i;
            float ir  = acc[0][i] + g_bbig[0 * H + h];
            float iz  = acc[1][i] + g_bbig[1 * H + h];
            float inn = acc[2][i] + g_bbig[2 * H + h];
            float hr  = acc[3][i] + g_bbig[3 * H + h];
            float hz  = acc[4][i] + g_bbig[4 * H + h];
            float hn  = acc[5][i] + g_bbig[5 * H + h];
            float h3  = acc[6][i] + g_bbig[6 * H + h];
            float r = sigmoidf_(ir + hr);
            float z = sigmoidf_(iz + hz);
            float n = tanhf(inn + r * hn);
            float hnew = (1.0f - z) * n + z * h3;
            __stcs(&out[((size_t)t * B + b) * H + h], hnew);
            __stcg(&g_hx[b * H + h], hnew);
        }

        grid_barrier(gen);
    }
}

// ---------------- finalize: append hx, cx after outputs ----------------
__global__ void k_finalize(float* __restrict__ out) {
    int i = blockIdx.x * blockDim.x + threadIdx.x;
    if (i < B * H) {
        out[(size_t)T_STEPS * B * H + i] = g_hx[i];
        out[(size_t)T_STEPS * B * H + B * H + i] = g_cx[i];
    }
}

// ---------------- host ----------------
extern "C" void kernel_launch(void* const* d_in, const int* in_sizes, int n_in,
                              void* d_out, int out_size) {
    (void)in_sizes; (void)n_in; (void)out_size;
    const float* inputs   = (const float*)d_in[0];
    const float* lstm_Wih = (const float*)d_in[1];
    const float* lstm_Whh = (const float*)d_in[2];
    const float* lstm_bih = (const float*)d_in[3];
    const float* lstm_bhh = (const float*)d_in[4];
    const float* phase    = (const float*)d_in[5];
    const float* fe_W     = (const float*)d_in[6];
    const float* fe_b     = (const float*)d_in[7];
    const float* gru_Wih  = (const float*)d_in[8];
    const float* gru_Whh  = (const float*)d_in[9];
    const float* gru_bih  = (const float*)d_in[10];
    const float* gru_bhh  = (const float*)d_in[11];
    float* out = (float*)d_out;

    float *pM, *pWbig, *pXproj;
    cudaGetSymbolAddress((void**)&pM, g_M);
    cudaGetSymbolAddress((void**)&pWbig, g_Wbig);
    cudaGetSymbolAddress((void**)&pXproj, g_Xproj);

    // state init (graph replays must be deterministic)
    k_init<<<(B * H + 255) / 256, 256>>>();

    // precompute folded weights
    k_whc<<<(G4 * H + 255) / 256, 256>>>(lstm_Wih, lstm_Whh);

    // M = phase @ fe_W^T
    gemm_nt<<<dim3(H / 32, H / 32), 256>>>(phase, fe_W, pM, nullptr, nullptr,
                                           H, H, H, H, 0);
    // Wbig[:, 0:1536] = M @ gru_Wih^T
    gemm_nt<<<dim3(H / 32, 1536 / 32), 256>>>(pM, gru_Wih, pWbig, nullptr, nullptr,
                                              H, H, H, ZW, 0);
    // Wbig[:, 1536:3072] = M @ gru_Whh^T
    gemm_nt<<<dim3(H / 32, 1536 / 32), 256>>>(pM, gru_Whh, pWbig, nullptr, nullptr,
                                              H, H, H, ZW, 1536);
    // Wbig[:, 3072:3584] = M
    k_copyM<<<(H * H + 255) / 256, 256>>>();

    // fused GRU-side bias
    k_bbig<<<(ZW + 255) / 256, 256>>>(fe_b, gru_Wih, gru_Whh, gru_bih, gru_bhh);

    // Xproj[t,b,:] = x @ Wih[:, :D]^T + bih + bhh  (big parallel GEMM)
    gemm_nt<<<dim3((T_STEPS * B) / 32, G4 / 32), 256>>>(
        inputs, lstm_Wih, pXproj, lstm_bih, lstm_bhh,
        D, D, D + H, G4, 0);

    // ONE persistent kernel for the whole recurrence (keeps graph tiny)
    k_recur<<<NBLK, 256>>>(out);

    k_finalize<<<(B * H + 255) / 256, 256>>>(out);
}

// round 5
// speedup vs baseline: 1.0490x; 1.0022x over previous
#include <cuda_runtime.h>
#include <math.h>

// Problem dims
#define T_STEPS 512
#define B 256
#define D 256
#define H 512
#define G4 2048        // 4*H (LSTM gates)
#define ZW 3584        // 3*H (gi) + 3*H (gh) + H (h3)
#define NBLK 128       // persistent grid: (B/32) * (H/32) = 8*16

// ---------------- device scratch (no allocation allowed) ----------------
__device__ float g_Xproj[(size_t)T_STEPS * B * G4]; // per-step input projection + biases
__device__ float g_Whc[G4 * H];                     // Wih[:,D:] + Whh   [j][k]
__device__ float g_M[H * H];                        // phase @ fe_W^T    [k][j]
__device__ float g_Wbig[H * ZW];                    // [k][j]: [M@Wih_g^T | M@Whh_g^T | M]
__device__ float g_bbig[ZW];
__device__ float g_hx[B * H];
__device__ float g_cx[B * H];
__device__ float g_h1[B * H];

// grid-barrier state (persists across graph replays; gen is re-read at entry)
__device__ unsigned g_count = 0;
__device__ volatile unsigned g_sense = 0;

__device__ __forceinline__ float sigmoidf_(float x) {
    return 1.0f / (1.0f + expf(-x));
}

// ---------------- init ----------------
__global__ void k_init() {
    int i = blockIdx.x * blockDim.x + threadIdx.x;
    if (i < B * H) { g_hx[i] = 0.0f; g_cx[i] = 0.0f; }
}

// ---------------- Whc = Wih[:, D:] + Whh ----------------
__global__ void k_whc(const float* __restrict__ Wih, const float* __restrict__ Whh) {
    int idx = blockIdx.x * blockDim.x + threadIdx.x;
    if (idx < G4 * H) {
        int j = idx >> 9;
        int k = idx & 511;
        g_Whc[idx] = Wih[(size_t)j * (D + H) + D + k] + Whh[idx];
    }
}

// ---------------- generic NT GEMM (precompute only) ----------------
__global__ __launch_bounds__(256) void gemm_nt(
    const float* __restrict__ A, const float* __restrict__ Bm, float* __restrict__ C,
    const float* __restrict__ bias1, const float* __restrict__ bias2,
    int K, int lda, int ldb, int ldc, int coloff)
{
    __shared__ float sA[32][33];
    __shared__ float sB[32][33];
    int t = threadIdx.x;
    int i0 = blockIdx.x * 32, j0 = blockIdx.y * 32;
    int tx = t & 15, ty = t >> 4;
    float a00 = 0.f, a01 = 0.f, a10 = 0.f, a11 = 0.f;
    for (int l0 = 0; l0 < K; l0 += 32) {
        #pragma unroll
        for (int i = 0; i < 4; i++) {
            int e = t + i * 256; int r = e >> 5, cc = e & 31;
            sA[r][cc] = A[(size_t)(i0 + r) * lda + l0 + cc];
            sB[r][cc] = Bm[(size_t)(j0 + r) * ldb + l0 + cc];
        }
        __syncthreads();
        #pragma unroll
        for (int ll = 0; ll < 32; ll++) {
            float x0 = sA[ty * 2][ll],     x1 = sA[ty * 2 + 1][ll];
            float y0 = sB[tx * 2][ll],     y1 = sB[tx * 2 + 1][ll];
            a00 += x0 * y0; a01 += x0 * y1; a10 += x1 * y0; a11 += x1 * y1;
        }
        __syncthreads();
    }
    int iR = i0 + ty * 2;
    int jC = j0 + tx * 2;
    float acc[2][2] = {{a00, a01}, {a10, a11}};
    #pragma unroll
    for (int r = 0; r < 2; r++) {
        #pragma unroll
        for (int c = 0; c < 2; c++) {
            float v = acc[r][c];
            int j = jC + c;
            if (bias1) v += bias1[j];
            if (bias2) v += bias2[j];
            C[(size_t)(iR + r) * ldc + coloff + j] = v;
        }
    }
}

// ---------------- copy M into Wbig block 6 ----------------
__global__ void k_copyM() {
    int idx = blockIdx.x * blockDim.x + threadIdx.x;
    if (idx < H * H) {
        int k = idx >> 9, j = idx & 511;
        g_Wbig[(size_t)k * ZW + 3072 + j] = g_M[idx];
    }
}

// ---------------- fused bias ----------------
__global__ void k_bbig(const float* __restrict__ feb,
                       const float* __restrict__ gWih, const float* __restrict__ gWhh,
                       const float* __restrict__ gbih, const float* __restrict__ gbhh) {
    int j = blockIdx.x * blockDim.x + threadIdx.x;
    if (j >= ZW) return;
    float s;
    if (j < 1536) {
        const float* w = gWih + (size_t)j * H;
        s = gbih[j];
        for (int k = 0; k < H; k++) s += feb[k] * w[k];
    } else if (j < 3072) {
        int jj = j - 1536;
        const float* w = gWhh + (size_t)jj * H;
        s = gbhh[jj];
        for (int k = 0; k < H; k++) s += feb[k] * w[k];
    } else {
        s = feb[j - 3072];
    }
    g_bbig[j] = s;
}

// ---------------- software grid barrier (all NBLK blocks resident) ----------------
__device__ __forceinline__ void grid_barrier(unsigned& gen) {
    __syncthreads();
    if (threadIdx.x == 0) {
        __threadfence();  // publish this block's global writes
        if (atomicAdd(&g_count, 1u) == NBLK - 1) {
            g_count = 0;
            __threadfence();
            g_sense = gen + 1;  // release
        } else {
            while (g_sense == gen) { }
            __threadfence();
        }
        gen = gen + 1;
    }
    __syncthreads();
}

// ---------------- persistent recurrence kernel: all 512 steps ----------------
// grid = 128 blocks x 256 threads, all co-resident.
// Block (bq, jq): bq = bid & 7 -> batch rows b0..b0+31; jq = bid >> 3 -> cols j0..j0+31.
__global__ __launch_bounds__(256) void k_recur(float* __restrict__ out) {
    __shared__ float sHT[32][36];       // hidden tile, k-major: sHT[k][row]
    __shared__ float sW[7][32][36];     // weight tiles (stage1: [blk][col][k], stage2: [blk][k][col])

    int tid = threadIdx.x;
    int bid = blockIdx.x;
    int b0 = (bid & 7) * 32;
    int j0 = (bid >> 3) * 32;
    int c   = tid & 31;           // output column within tile
    int rg  = tid >> 5;           // row group: rows rg*4 .. rg*4+3
    int kk4 = (tid & 7) * 4;      // float4 k-offset for loads
    int r8  = tid >> 3;           // 0..31: row/col index for loads
    int h   = j0 + c;

    unsigned gen = 0;
    if (tid == 0) gen = g_sense;  // survive graph replays

    for (int t = 0; t < T_STEPS; t++) {
        float acc[7][4];

        // ================= stage 1: LSTM gates =================
        #pragma unroll
        for (int blk = 0; blk < 4; blk++)
            #pragma unroll
            for (int i = 0; i < 4; i++) acc[blk][i] = 0.f;

        for (int k0 = 0; k0 < H; k0 += 32) {
            // hx tile (cross-block producer -> bypass L1), store transposed
            {
                float4 v = __ldcg(reinterpret_cast<const float4*>(
                    &g_hx[(b0 + r8) * H + k0 + kk4]));
                sHT[kk4 + 0][r8] = v.x;
                sHT[kk4 + 1][r8] = v.y;
                sHT[kk4 + 2][r8] = v.z;
                sHT[kk4 + 3][r8] = v.w;
            }
            // Whc tiles: sW[blk][col][k]
            #pragma unroll
            for (int blk = 0; blk < 4; blk++) {
                float4 w = *reinterpret_cast<const float4*>(
                    &g_Whc[(size_t)(blk * H + j0 + r8) * H + k0 + kk4]);
                *reinterpret_cast<float4*>(&sW[blk][r8][kk4]) = w;
            }
            __syncthreads();
            #pragma unroll
            for (int kk = 0; kk < 32; kk++) {
                float4 x = *reinterpret_cast<const float4*>(&sHT[kk][rg * 4]);
                #pragma unroll
                for (int blk = 0; blk < 4; blk++) {
                    float w = sW[blk][c][kk];
                    acc[blk][0] += x.x * w;
                    acc[blk][1] += x.y * w;
                    acc[blk][2] += x.z * w;
                    acc[blk][3] += x.w * w;
                }
            }
            __syncthreads();
        }
        #pragma unroll
        for (int i = 0; i < 4; i++) {
            int b = b0 + rg * 4 + i;
            size_t xb = ((size_t)t * B + b) * G4;
            float gi = acc[0][i] + __ldcs(&g_Xproj[xb + 0 * H + h]);
            float gf = acc[1][i] + __ldcs(&g_Xproj[xb + 1 * H + h]);
            float gg = acc[2][i] + __ldcs(&g_Xproj[xb + 2 * H + h]);
            float go = acc[3][i] + __ldcs(&g_Xproj[xb + 3 * H + h]);
            float iv = sigmoidf_(gi);
            float fv = sigmoidf_(gf);
            float gv = tanhf(gg);
            float ov = sigmoidf_(go);
            float cp = g_cx[b * H + h];          // same thread wrote it last step
            float cn = fv * cp + iv * gv;
            g_cx[b * H + h] = cn;
            __stcg(&g_h1[b * H + h], ov * tanhf(cn));
        }

        grid_barrier(gen);

        // ================= stage 2: phase/fe folded GRU =================
        #pragma unroll
        for (int blk = 0; blk < 7; blk++)
            #pragma unroll
            for (int i = 0; i < 4; i++) acc[blk][i] = 0.f;

        for (int k0 = 0; k0 < H; k0 += 32) {
            {
                float4 v = __ldcg(reinterpret_cast<const float4*>(
                    &g_h1[(b0 + r8) * H + k0 + kk4]));
                sHT[kk4 + 0][r8] = v.x;
                sHT[kk4 + 1][r8] = v.y;
                sHT[kk4 + 2][r8] = v.z;
                sHT[kk4 + 3][r8] = v.w;
            }
            // Wbig tiles: sW[blk][k][col]
            #pragma unroll
            for (int blk = 0; blk < 7; blk++) {
                float4 w = *reinterpret_cast<const float4*>(
                    &g_Wbig[(size_t)(k0 + r8) * ZW + blk * H + j0 + kk4]);
                *reinterpret_cast<float4*>(&sW[blk][r8][kk4]) = w;
            }
            __syncthreads();
            #pragma unroll
            for (int kk = 0; kk < 32; kk++) {
                float4 x = *reinterpret_cast<const float4*>(&sHT[kk][rg * 4]);
                #pragma unroll
                for (int blk = 0; blk < 7; blk++) {
                    float w = sW[blk][kk][c];
                    acc[blk][0] += x.x * w;
                    acc[blk][1] += x.y * w;
                    acc[blk][2] += x.z * w;
                    acc[blk][3] += x.w * w;
                }
            }
            __syncthreads();
        }
        #pragma unroll
        for (int i = 0; i < 4; i++) {
            int b = b0 + rg * 4 + i;
            float ir  = acc[0][i] + g_bbig[0 * H + h];
            float iz  = acc[1][i] + g_bbig[1 * H + h];
            float inn = acc[2][i] + g_bbig[2 * H + h];
            float hr  = acc[3][i] + g_bbig[3 * H + h];
            float hz  = acc[4][i] + g_bbig[4 * H + h];
            float hn  = acc[5][i] + g_bbig[5 * H + h];
            float h3  = acc[6][i] + g_bbig[6 * H + h];
            float r = sigmoidf_(ir + hr);
            float z = sigmoidf_(iz + hz);
            float n = tanhf(inn + r * hn);
            float hnew = (1.0f - z) * n + z * h3;
            __stcs(&out[((size_t)t * B + b) * H + h], hnew);
            __stcg(&g_hx[b * H + h], hnew);
        }

        grid_barrier(gen);
    }
}

// ---------------- finalize: append hx, cx after outputs ----------------
__global__ void k_finalize(float* __restrict__ out) {
    int i = blockIdx.x * blockDim.x + threadIdx.x;
    if (i < B * H) {
        out[(size_t)T_STEPS * B * H + i] = g_hx[i];
        out[(size_t)T_STEPS * B * H + B * H + i] = g_cx[i];
    }
}

// ---------------- host ----------------
extern "C" void kernel_launch(void* const* d_in, const int* in_sizes, int n_in,
                              void* d_out, int out_size) {
    (void)in_sizes; (void)n_in; (void)out_size;
    const float* inputs   = (const float*)d_in[0];
    const float* lstm_Wih = (const float*)d_in[1];
    const float* lstm_Whh = (const float*)d_in[2];
    const float* lstm_bih = (const float*)d_in[3];
    const float* lstm_bhh = (const float*)d_in[4];
    const float* phase    = (const float*)d_in[5];
    const float* fe_W     = (const float*)d_in[6];
    const float* fe_b     = (const float*)d_in[7];
    const float* gru_Wih  = (const float*)d_in[8];
    const float* gru_Whh  = (const float*)d_in[9];
    const float* gru_bih  = (const float*)d_in[10];
    const float* gru_bhh  = (const float*)d_in[11];
    float* out = (float*)d_out;

    float *pM, *pWbig, *pXproj;
    cudaGetSymbolAddress((void**)&pM, g_M);
    cudaGetSymbolAddress((void**)&pWbig, g_Wbig);
    cudaGetSymbolAddress((void**)&pXproj, g_Xproj);

    // state init (graph replays must be deterministic)
    k_init<<<(B * H + 255) / 256, 256>>>();

    // precompute folded weights
    k_whc<<<(G4 * H + 255) / 256, 256>>>(lstm_Wih, lstm_Whh);

    // M = phase @ fe_W^T
    gemm_nt<<<dim3(H / 32, H / 32), 256>>>(phase, fe_W, pM, nullptr, nullptr,
                                           H, H, H, H, 0);
    // Wbig[:, 0:1536] = M @ gru_Wih^T
    gemm_nt<<<dim3(H / 32, 1536 / 32), 256>>>(pM, gru_Wih, pWbig, nullptr, nullptr,
                                              H, H, H, ZW, 0);
    // Wbig[:, 1536:3072] = M @ gru_Whh^T
    gemm_nt<<<dim3(H / 32, 1536 / 32), 256>>>(pM, gru_Whh, pWbig, nullptr, nullptr,
                                              H, H, H, ZW, 1536);
    // Wbig[:, 3072:3584] = M
    k_copyM<<<(H * H + 255) / 256, 256>>>();

    // fused GRU-side bias
    k_bbig<<<(ZW + 255) / 256, 256>>>(fe_b, gru_Wih, gru_Whh, gru_bih, gru_bhh);

    // Xproj[t,b,:] = x @ Wih[:, :D]^T + bih + bhh  (big parallel GEMM)
    gemm_nt<<<dim3((T_STEPS * B) / 32, G4 / 32), 256>>>(
        inputs, lstm_Wih, pXproj, lstm_bih, lstm_bhh,
        D, D, D + H, G4, 0);

    // ONE persistent kernel for the whole recurrence (keeps graph tiny)
    k_recur<<<NBLK, 256>>>(out);

    k_finalize<<<(B * H + 255) / 256, 256>>>(out);
}

// round 7
// speedup vs baseline: 3.1943x; 3.0451x over previous
#include <cuda_runtime.h>
#include <cuda_bf16.h>
#include <math.h>
#include <stdint.h>

// ---------------- dims ----------------
#define T_STEPS 512
#define B 256
#define D 256
#define H 512
#define KFULL 768         // D + H concat-K for stage 1
#define N1 2048           // stage1 N: p = 4h+g
#define N2 4096           // stage2 N (padded): p = 8h+blk, blk 0..6 used
#define GB_N 128          // persistent grid (1 CTA/SM)

// smem chunk buffers: rows x 64 halves, padded row stride 72 halves (144B)
#define RSTR 144          // bytes per padded row
#define OFF_AH 0
#define OFF_AL (64 * RSTR)            // 9216
#define OFF_BH (2 * 64 * RSTR)        // 18432
#define OFF_BL (OFF_BH + 128 * RSTR)  // 36864
#define BUF_BYTES (OFF_BL + 128 * RSTR)  // 55296
#define DYN_SMEM (2 * BUF_BYTES + 256)

// ---------------- device scratch ----------------
__device__ __nv_bfloat16 g_in_h[(size_t)T_STEPS * B * D];
__device__ __nv_bfloat16 g_in_l[(size_t)T_STEPS * B * D];
__device__ __nv_bfloat16 g_W1h[(size_t)N1 * KFULL];
__device__ __nv_bfloat16 g_W1l[(size_t)N1 * KFULL];
__device__ __nv_bfloat16 g_W2ph[(size_t)N2 * H];
__device__ __nv_bfloat16 g_W2pl[(size_t)N2 * H];
__device__ float g_Mtmp[(size_t)H * H];     // (phase @ fe_W^T)[k][l]
__device__ float g_T2i[(size_t)1536 * H];   // (gru_Wih @ M^T)[j][k]
__device__ float g_T2h[(size_t)1536 * H];
__device__ float g_bbig[N2];
__device__ float g_bsum[N1];
__device__ float g_cx[B * H];
__device__ __nv_bfloat16 g_hx_h[B * H], g_hx_l[B * H];
__device__ __nv_bfloat16 g_h1_h[B * H], g_h1_l[B * H];
__device__ unsigned g_count = 0;
__device__ volatile unsigned g_sense = 0;

// ---------------- helpers ----------------
__device__ __forceinline__ float sigmoidf_(float x) { return 1.0f / (1.0f + expf(-x)); }

__device__ __forceinline__ void split2(float x, __nv_bfloat16& h, __nv_bfloat16& l) {
    h = __float2bfloat16_rn(x);
    l = __float2bfloat16_rn(x - __bfloat162float(h));
}

__device__ __forceinline__ uint32_t smem_u32(const void* p) {
    uint32_t a;
    asm("{ .reg .u64 t; cvta.to.shared.u64 t, %1; cvt.u32.u64 %0, t; }" : "=r"(a) : "l"(p));
    return a;
}

__device__ __forceinline__ void cpasync_cg(uint32_t dst, const void* src) {
    asm volatile("cp.async.cg.shared.global [%0], [%1], 16;" :: "r"(dst), "l"(src) : "memory");
}
__device__ __forceinline__ void cpasync_ca(uint32_t dst, const void* src) {
    asm volatile("cp.async.ca.shared.global [%0], [%1], 16;" :: "r"(dst), "l"(src) : "memory");
}
#define CP_COMMIT() asm volatile("cp.async.commit_group;" ::: "memory")
#define CP_WAIT1()  asm volatile("cp.async.wait_group 1;" ::: "memory")
#define CP_WAIT0()  asm volatile("cp.async.wait_group 0;" ::: "memory")

__device__ __forceinline__ void ldsm4(uint32_t r[4], uint32_t addr) {
    asm volatile("ldmatrix.sync.aligned.m8n8.x4.shared.b16 {%0,%1,%2,%3}, [%4];"
                 : "=r"(r[0]), "=r"(r[1]), "=r"(r[2]), "=r"(r[3]) : "r"(addr));
}

__device__ __forceinline__ void mma16816(float c[4], const uint32_t a[4],
                                         uint32_t b0, uint32_t b1) {
    asm volatile(
        "mma.sync.aligned.m16n8k16.row.col.f32.bf16.bf16.f32 "
        "{%0,%1,%2,%3}, {%4,%5,%6,%7}, {%8,%9}, {%0,%1,%2,%3};"
        : "+f"(c[0]), "+f"(c[1]), "+f"(c[2]), "+f"(c[3])
        : "r"(a[0]), "r"(a[1]), "r"(a[2]), "r"(a[3]), "r"(b0), "r"(b1));
}

__device__ __forceinline__ void st_cg_u16(__nv_bfloat16* p, __nv_bfloat16 v) {
    uint16_t u = __bfloat16_as_ushort(v);
    asm volatile("st.global.cg.u16 [%0], %1;" :: "l"(p), "h"(u) : "memory");
}

// ---- chunk loader: RA rows of A (hi/lo), 128 rows of B (hi/lo), 64 halves each ----
template <int RA>
__device__ __forceinline__ void load_chunk(
    uint32_t sbuf,
    const __nv_bfloat16* __restrict__ Ah, const __nv_bfloat16* __restrict__ Al, int lda,
    const __nv_bfloat16* __restrict__ Bh, const __nv_bfloat16* __restrict__ Bl, int ldb,
    int tid)
{
    #pragma unroll
    for (int i = 0; i < RA / 32; i++) {
        int seg = tid + i * 256;
        int row = seg >> 3, q = seg & 7;
        uint32_t d = (uint32_t)(row * RSTR + q * 16);
        const __nv_bfloat16* sh = Ah + (size_t)row * lda + q * 8;
        const __nv_bfloat16* sl = Al + (size_t)row * lda + q * 8;
        cpasync_cg(sbuf + OFF_AH + d, sh);
        cpasync_cg(sbuf + OFF_AL + d, sl);
    }
    #pragma unroll
    for (int i = 0; i < 4; i++) {
        int seg = tid + i * 256;
        int row = seg >> 3, q = seg & 7;
        uint32_t d = (uint32_t)(row * RSTR + q * 16);
        cpasync_ca(sbuf + OFF_BH + d, Bh + (size_t)row * ldb + q * 8);
        cpasync_ca(sbuf + OFF_BL + d, Bl + (size_t)row * ldb + q * 8);
    }
}

// ---- warp MMA over one K=64 chunk. Warp tile: 32 rows x (NB8*8) cols, 3 split terms ----
template <int NB8>
__device__ __forceinline__ void chunk_mma(uint32_t sbuf, int mbase, int nbase,
                                          int lane, float c[2][NB8][4])
{
    int lr = lane & 15, ls = lane >> 4;
    uint32_t aoff = (uint32_t)(lr * RSTR + ls * 16);
    uint32_t aAh = sbuf + OFF_AH + (uint32_t)mbase * RSTR + aoff;
    uint32_t aAl = sbuf + OFF_AL + (uint32_t)mbase * RSTR + aoff;
    uint32_t aBh = sbuf + OFF_BH + (uint32_t)nbase * RSTR + aoff;
    uint32_t aBl = sbuf + OFF_BL + (uint32_t)nbase * RSTR + aoff;
    #pragma unroll
    for (int kk = 0; kk < 4; kk++) {
        uint32_t ko = kk * 32;
        uint32_t Ah[2][4], Al[2][4], Bh[NB8 / 2][4], Bl[NB8 / 2][4];
        ldsm4(Ah[0], aAh + ko);
        ldsm4(Ah[1], aAh + 16 * RSTR + ko);
        ldsm4(Al[0], aAl + ko);
        ldsm4(Al[1], aAl + 16 * RSTR + ko);
        #pragma unroll
        for (int j = 0; j < NB8 / 2; j++) {
            ldsm4(Bh[j], aBh + j * 16 * RSTR + ko);
            ldsm4(Bl[j], aBl + j * 16 * RSTR + ko);
        }
        #pragma unroll
        for (int mi = 0; mi < 2; mi++) {
            #pragma unroll
            for (int j = 0; j < NB8 / 2; j++) {
                mma16816(c[mi][2 * j],     Ah[mi], Bh[j][0], Bh[j][2]);
                mma16816(c[mi][2 * j + 1], Ah[mi], Bh[j][1], Bh[j][3]);
                mma16816(c[mi][2 * j],     Al[mi], Bh[j][0], Bh[j][2]);
                mma16816(c[mi][2 * j + 1], Al[mi], Bh[j][1], Bh[j][3]);
                mma16816(c[mi][2 * j],     Ah[mi], Bl[j][0], Bl[j][2]);
                mma16816(c[mi][2 * j + 1], Ah[mi], Bl[j][1], Bl[j][3]);
            }
        }
    }
}

// ---- C fragments -> smem float staging (stride 132 floats) ----
template <int NB8>
__device__ __forceinline__ void store_C(float* sC, int mbase, int nbase,
                                        int lane, float c[2][NB8][4])
{
    int tq = lane >> 2, tr = lane & 3;
    #pragma unroll
    for (int mi = 0; mi < 2; mi++) {
        #pragma unroll
        for (int ni = 0; ni < NB8; ni++) {
            int r = mbase + mi * 16 + tq;
            int col = nbase + ni * 8 + tr * 2;
            *(float2*)&sC[(size_t)r * 132 + col] = make_float2(c[mi][ni][0], c[mi][ni][1]);
            *(float2*)&sC[(size_t)(r + 8) * 132 + col] = make_float2(c[mi][ni][2], c[mi][ni][3]);
        }
    }
}

// ---------------- grid barrier ----------------
__device__ __forceinline__ void grid_barrier(unsigned& gen) {
    __syncthreads();
    if (threadIdx.x == 0) {
        __threadfence();
        if (atomicAdd(&g_count, 1u) == GB_N - 1) {
            g_count = 0;
            __threadfence();
            g_sense = gen + 1;
        } else {
            while (g_sense == gen) { }
            __threadfence();
        }
        gen = gen + 1;
    }
    __syncthreads();
}

// ---------------- precompute kernels ----------------
__global__ void k_init() {
    int i = blockIdx.x * blockDim.x + threadIdx.x;
    if (i < B * H) {
        g_hx_h[i] = __ushort_as_bfloat16(0);
        g_hx_l[i] = __ushort_as_bfloat16(0);
    }
}

__global__ void k_pack_inputs(const float* __restrict__ src) {
    size_t n = (size_t)T_STEPS * B * D;
    for (size_t i = blockIdx.x * (size_t)blockDim.x + threadIdx.x; i < n;
         i += (size_t)gridDim.x * blockDim.x) {
        __nv_bfloat16 h, l;
        split2(src[i], h, l);
        g_in_h[i] = h; g_in_l[i] = l;
    }
}

// W1[p=4h+g][k] = Wih[g*512+h][k] (+ Whh[g*512+h][k-256] for k>=256)
__global__ void k_pack_w1(const float* __restrict__ Wih, const float* __restrict__ Whh) {
    size_t n = (size_t)N1 * KFULL;
    for (size_t i = blockIdx.x * (size_t)blockDim.x + threadIdx.x; i < n;
         i += (size_t)gridDim.x * blockDim.x) {
        int p = (int)(i / KFULL), k = (int)(i % KFULL);
        int hh = p >> 2, g = p & 3;
        int j = g * H + hh;
        float v = Wih[(size_t)j * KFULL + k];
        if (k >= D) v += Whh[(size_t)j * H + (k - D)];
        __nv_bfloat16 h, l;
        split2(v, h, l);
        g_W1h[i] = h; g_W1l[i] = l;
    }
}

// fp32 NT GEMM: C[i][j] = sum_l A[i][l] * Bm[j][l]
__global__ __launch_bounds__(256) void gemm_nt(
    const float* __restrict__ A, const float* __restrict__ Bm, float* __restrict__ C,
    int K, int lda, int ldb, int ldc)
{
    __shared__ float sA[32][33];
    __shared__ float sB[32][33];
    int t = threadIdx.x;
    int i0 = blockIdx.x * 32, j0 = blockIdx.y * 32;
    int tx = t & 15, ty = t >> 4;
    float a00 = 0.f, a01 = 0.f, a10 = 0.f, a11 = 0.f;
    for (int l0 = 0; l0 < K; l0 += 32) {
        #pragma unroll
        for (int i = 0; i < 4; i++) {
            int e = t + i * 256; int r = e >> 5, cc = e & 31;
            sA[r][cc] = A[(size_t)(i0 + r) * lda + l0 + cc];
            sB[r][cc] = Bm[(size_t)(j0 + r) * ldb + l0 + cc];
        }
        __syncthreads();
        #pragma unroll
        for (int ll = 0; ll < 32; ll++) {
            float x0 = sA[ty * 2][ll], x1 = sA[ty * 2 + 1][ll];
            float y0 = sB[tx * 2][ll], y1 = sB[tx * 2 + 1][ll];
            a00 += x0 * y0; a01 += x0 * y1; a10 += x1 * y0; a11 += x1 * y1;
        }
        __syncthreads();
    }
    C[(size_t)(i0 + ty * 2) * ldc + j0 + tx * 2]         = a00;
    C[(size_t)(i0 + ty * 2) * ldc + j0 + tx * 2 + 1]     = a01;
    C[(size_t)(i0 + ty * 2 + 1) * ldc + j0 + tx * 2]     = a10;
    C[(size_t)(i0 + ty * 2 + 1) * ldc + j0 + tx * 2 + 1] = a11;
}

// W2[p=8h+blk][k]: blk0..2 = T2i[blk*512+h][k]; blk3..5 = T2h[(blk-3)*512+h][k];
// blk6 = M[k][h]; blk7 = 0
__global__ void k_pack_w2() {
    size_t n = (size_t)N2 * H;
    for (size_t i = blockIdx.x * (size_t)blockDim.x + threadIdx.x; i < n;
         i += (size_t)gridDim.x * blockDim.x) {
        int p = (int)(i >> 9), k = (int)(i & 511);
        int hh = p >> 3, blk = p & 7;
        float v;
        if (blk < 3)       v = g_T2i[(size_t)(blk * H + hh) * H + k];
        else if (blk < 6)  v = g_T2h[(size_t)((blk - 3) * H + hh) * H + k];
        else if (blk == 6) v = g_Mtmp[(size_t)k * H + hh];
        else               v = 0.0f;
        __nv_bfloat16 h, l;
        split2(v, h, l);
        g_W2ph[i] = h; g_W2pl[i] = l;
    }
}

__global__ void k_bbig_perm(const float* __restrict__ feb,
                            const float* __restrict__ gWih, const float* __restrict__ gWhh,
                            const float* __restrict__ gbih, const float* __restrict__ gbhh) {
    int p = blockIdx.x * blockDim.x + threadIdx.x;
    if (p >= N2) return;
    int hh = p >> 3, blk = p & 7;
    float s = 0.0f;
    if (blk < 3) {
        int j = blk * H + hh;
        const float* w = gWih + (size_t)j * H;
        s = gbih[j];
        for (int k = 0; k < H; k++) s += feb[k] * w[k];
    } else if (blk < 6) {
        int j = (blk - 3) * H + hh;
        const float* w = gWhh + (size_t)j * H;
        s = gbhh[j];
        for (int k = 0; k < H; k++) s += feb[k] * w[k];
    } else if (blk == 6) {
        s = feb[hh];
    }
    g_bbig[p] = s;
}

__global__ void k_bsum_perm(const float* __restrict__ bih, const float* __restrict__ bhh) {
    int p = blockIdx.x * blockDim.x + threadIdx.x;
    if (p < N1) {
        int hh = p >> 2, g = p & 3;
        int j = g * H + hh;
        g_bsum[p] = bih[j] + bhh[j];
    }
}

// ---------------- persistent recurrence: mma.sync warp GEMMs ----------------
__global__ void __launch_bounds__(256, 1) k_recur(float* __restrict__ out) {
    extern __shared__ char smraw[];
    uint32_t sb0 = (smem_u32(smraw) + 127u) & ~127u;
    char* smbase = smraw + (sb0 - smem_u32(smraw));
    uint32_t sbuf[2] = { sb0, sb0 + BUF_BYTES };
    float* sC = (float*)smbase;   // C staging reuses buffer 0 region

    int tid = threadIdx.x, lane = tid & 31, w = tid >> 5, bid = blockIdx.x;

    // stage1 mapping: tile 32(M) x 128(N); warp tile 32x16 (NB8=2)
    int mt1 = bid >> 4, nt1 = bid & 15;
    int m1row0 = mt1 * 32;
    int nb1 = w * 16;
    const __nv_bfloat16* W1hB = g_W1h + (size_t)(nt1 * 128) * KFULL;
    const __nv_bfloat16* W1lB = g_W1l + (size_t)(nt1 * 128) * KFULL;

    // stage2 mapping: tile 64 x 128; warp tile 32x32 (NB8=4)
    int mt2 = bid >> 5, nt2 = bid & 31;
    int m2row0 = mt2 * 64;
    int mb2 = (w >> 2) * 32, nb2 = (w & 3) * 32;
    const __nv_bfloat16* W2hB = g_W2ph + (size_t)(nt2 * 128) * H;
    const __nv_bfloat16* W2lB = g_W2pl + (size_t)(nt2 * 128) * H;

    float cxr[4] = {0.f, 0.f, 0.f, 0.f};
    unsigned gen = 0;
    if (tid == 0) gen = g_sense;     // survive graph replays

    for (int t = 0; t < T_STEPS; t++) {
        // ================= stage 1: gates = [x_t | hx] @ W1^T (K=768) =================
        {
            auto a1 = [&](int kc, const __nv_bfloat16*& ph, const __nv_bfloat16*& pl, int& lda) {
                if (kc < 4) {
                    ph = g_in_h + ((size_t)t * B + m1row0) * D + kc * 64;
                    pl = g_in_l + ((size_t)t * B + m1row0) * D + kc * 64;
                    lda = D;
                } else {
                    ph = g_hx_h + (size_t)m1row0 * H + (kc * 64 - D);
                    pl = g_hx_l + (size_t)m1row0 * H + (kc * 64 - D);
                    lda = H;
                }
            };
            float c1[2][2][4];
            #pragma unroll
            for (int a = 0; a < 2; a++)
                #pragma unroll
                for (int b2 = 0; b2 < 2; b2++)
                    #pragma unroll
                    for (int q = 0; q < 4; q++) c1[a][b2][q] = 0.f;

            { const __nv_bfloat16 *ph, *pl; int lda; a1(0, ph, pl, lda);
              load_chunk<32>(sbuf[0], ph, pl, lda, W1hB, W1lB, KFULL, tid); CP_COMMIT(); }
            for (int kc = 0; kc < 12; kc++) {
                if (kc < 11) {
                    const __nv_bfloat16 *ph, *pl; int lda; a1(kc + 1, ph, pl, lda);
                    load_chunk<32>(sbuf[(kc + 1) & 1], ph, pl, lda,
                                   W1hB + (kc + 1) * 64, W1lB + (kc + 1) * 64, KFULL, tid);
                    CP_COMMIT(); CP_WAIT1();
                } else {
                    CP_WAIT0();
                }
                __syncthreads();
                chunk_mma<2>(sbuf[kc & 1], 0, nb1, lane, c1);
                __syncthreads();
            }
            store_C<2>(sC, 0, nb1, lane, c1);
        }
        __syncthreads();
        // EW1: LSTM elementwise (cols = 4h+g), cx in registers
        #pragma unroll
        for (int i = 0; i < 4; i++) {
            int cid = tid + i * 256;
            int r = cid >> 5, hl = cid & 31;
            int pb = nt1 * 128 + hl * 4;
            float gi = sC[(size_t)r * 132 + hl * 4 + 0] + __ldg(&g_bsum[pb + 0]);
            float gf = sC[(size_t)r * 132 + hl * 4 + 1] + __ldg(&g_bsum[pb + 1]);
            float gg = sC[(size_t)r * 132 + hl * 4 + 2] + __ldg(&g_bsum[pb + 2]);
            float go = sC[(size_t)r * 132 + hl * 4 + 3] + __ldg(&g_bsum[pb + 3]);
            float iv = sigmoidf_(gi);
            float fv = sigmoidf_(gf);
            float gv = tanhf(gg);
            float ov = sigmoidf_(go);
            float cn = fv * cxr[i] + iv * gv;
            cxr[i] = cn;
            float h1v = ov * tanhf(cn);
            int b = m1row0 + r;
            int hg = nt1 * 32 + hl;
            __nv_bfloat16 hh, ll;
            split2(h1v, hh, ll);
            st_cg_u16(&g_h1_h[(size_t)b * H + hg], hh);
            st_cg_u16(&g_h1_l[(size_t)b * H + hg], ll);
            if (t == T_STEPS - 1) g_cx[(size_t)b * H + hg] = cn;
        }
        grid_barrier(gen);

        // ================= stage 2: Z = h1 @ W2^T (K=512) =================
        {
            float c2[2][4][4];
            #pragma unroll
            for (int a = 0; a < 2; a++)
                #pragma unroll
                for (int b2 = 0; b2 < 4; b2++)
                    #pragma unroll
                    for (int q = 0; q < 4; q++) c2[a][b2][q] = 0.f;

            load_chunk<64>(sbuf[0],
                           g_h1_h + (size_t)m2row0 * H, g_h1_l + (size_t)m2row0 * H, H,
                           W2hB, W2lB, H, tid);
            CP_COMMIT();
            for (int kc = 0; kc < 8; kc++) {
                if (kc < 7) {
                    load_chunk<64>(sbuf[(kc + 1) & 1],
                                   g_h1_h + (size_t)m2row0 * H + (kc + 1) * 64,
                                   g_h1_l + (size_t)m2row0 * H + (kc + 1) * 64, H,
                                   W2hB + (kc + 1) * 64, W2lB + (kc + 1) * 64, H, tid);
                    CP_COMMIT(); CP_WAIT1();
                } else {
                    CP_WAIT0();
                }
                __syncthreads();
                chunk_mma<4>(sbuf[kc & 1], mb2, nb2, lane, c2);
                __syncthreads();
            }
            store_C<4>(sC, mb2, nb2, lane, c2);
        }
        __syncthreads();
        // EW2: GRU elementwise (cols = 8h+blk, blk 0..6)
        #pragma unroll
        for (int i = 0; i < 4; i++) {
            int cid = tid + i * 256;
            int r = cid >> 4, hl = cid & 15;
            int pb = nt2 * 128 + hl * 8;
            const float* cc = &sC[(size_t)r * 132 + hl * 8];
            float ir  = cc[0] + __ldg(&g_bbig[pb + 0]);
            float izv = cc[1] + __ldg(&g_bbig[pb + 1]);
            float inn = cc[2] + __ldg(&g_bbig[pb + 2]);
            float hr  = cc[3] + __ldg(&g_bbig[pb + 3]);
            float hz  = cc[4] + __ldg(&g_bbig[pb + 4]);
            float hn  = cc[5] + __ldg(&g_bbig[pb + 5]);
            float h3  = cc[6] + __ldg(&g_bbig[pb + 6]);
            float rv = sigmoidf_(ir + hr);
            float zz = sigmoidf_(izv + hz);
            float nn = tanhf(inn + rv * hn);
            float hnew = (1.0f - zz) * nn + zz * h3;
            int b = m2row0 + r;
            int hg = nt2 * 16 + hl;
            out[((size_t)t * B + b) * H + hg] = hnew;
            __nv_bfloat16 hh, ll;
            split2(hnew, hh, ll);
            st_cg_u16(&g_hx_h[(size_t)b * H + hg], hh);
            st_cg_u16(&g_hx_l[(size_t)b * H + hg], ll);
        }
        grid_barrier(gen);
    }
}

// ---------------- finalize: hx = out[T-1], cx ----------------
__global__ void k_finalize(float* __restrict__ out) {
    int i = blockIdx.x * blockDim.x + threadIdx.x;
    if (i < B * H) {
        out[(size_t)T_STEPS * B * H + i] = out[(size_t)(T_STEPS - 1) * B * H + i];
        out[(size_t)T_STEPS * B * H + B * H + i] = g_cx[i];
    }
}

// ---------------- host ----------------
extern "C" void kernel_launch(void* const* d_in, const int* in_sizes, int n_in,
                              void* d_out, int out_size) {
    (void)in_sizes; (void)n_in; (void)out_size;
    const float* inputs   = (const float*)d_in[0];
    const float* lstm_Wih = (const float*)d_in[1];
    const float* lstm_Whh = (const float*)d_in[2];
    const float* lstm_bih = (const float*)d_in[3];
    const float* lstm_bhh = (const float*)d_in[4];
    const float* phase    = (const float*)d_in[5];
    const float* fe_W     = (const float*)d_in[6];
    const float* fe_b     = (const float*)d_in[7];
    const float* gru_Wih  = (const float*)d_in[8];
    const float* gru_Whh  = (const float*)d_in[9];
    const float* gru_bih  = (const float*)d_in[10];
    const float* gru_bhh  = (const float*)d_in[11];
    float* out = (float*)d_out;

    float *pM, *pT2i, *pT2h;
    cudaGetSymbolAddress((void**)&pM, g_Mtmp);
    cudaGetSymbolAddress((void**)&pT2i, g_T2i);
    cudaGetSymbolAddress((void**)&pT2h, g_T2h);

    cudaFuncSetAttribute(k_recur, cudaFuncAttributeMaxDynamicSharedMemorySize, DYN_SMEM);

    k_init<<<(B * H + 255) / 256, 256>>>();
    k_pack_inputs<<<2048, 256>>>(inputs);
    k_pack_w1<<<2048, 256>>>(lstm_Wih, lstm_Whh);

    // Mtmp[k][l] = sum_j phase[k][j] * fe_W[l][j]
    gemm_nt<<<dim3(H / 32, H / 32), 256>>>(phase, fe_W, pM, H, H, H, H);
    // T2i[j][k] = sum_l gru_Wih[j][l] * Mtmp[k][l]
    gemm_nt<<<dim3(1536 / 32, H / 32), 256>>>(gru_Wih, pM, pT2i, H, H, H, H);
    // T2h[j][k] = sum_l gru_Whh[j][l] * Mtmp[k][l]
    gemm_nt<<<dim3(1536 / 32, H / 32), 256>>>(gru_Whh, pM, pT2h, H, H, H, H);

    k_pack_w2<<<4096, 256>>>();
    k_bbig_perm<<<(N2 + 255) / 256, 256>>>(fe_b, gru_Wih, gru_Whh, gru_bih, gru_bhh);
    k_bsum_perm<<<(N1 + 255) / 256, 256>>>(lstm_bih, lstm_bhh);

    // full 512-step recurrence in one persistent warp-MMA kernel
    k_recur<<<GB_N, 256, DYN_SMEM>>>(out);

    k_finalize<<<(B * H + 255) / 256, 256>>>(out);
}

// round 8
// speedup vs baseline: 3.2903x; 1.0300x over previous
#include <cuda_runtime.h>
#include <cuda_bf16.h>
#include <math.h>
#include <stdint.h>

// ---------------- dims ----------------
#define T_STEPS 512
#define B 256
#define D 256
#define H 512
#define KFULL 768         // D + H concat-K for stage 1
#define N1 2048           // stage1 N: p = 4h+g
#define N2 4096           // stage2 N (padded): p = 8h+blk, blk 0..6 used
#define GB_N 128          // persistent grid (1 CTA/SM)

// smem chunk buffers: rows x 64 halves, padded row stride 72 halves (144B)
#define RSTR 144
#define OFF_AH 0
#define OFF_AL (64 * RSTR)
#define OFF_BH (2 * 64 * RSTR)
#define OFF_BL (OFF_BH + 128 * RSTR)
#define BUF_BYTES (OFF_BL + 128 * RSTR)      // 55296
#define SC_BYTES (64 * 132 * 4)              // 33792 float staging
#define DYN_SMEM (2 * BUF_BYTES + SC_BYTES + 256)

// ---------------- device scratch ----------------
__device__ __nv_bfloat16 g_in_h[(size_t)T_STEPS * B * D];
__device__ __nv_bfloat16 g_in_l[(size_t)T_STEPS * B * D];
__device__ __nv_bfloat16 g_W1h[(size_t)N1 * KFULL];
__device__ __nv_bfloat16 g_W1l[(size_t)N1 * KFULL];
__device__ __nv_bfloat16 g_W2ph[(size_t)N2 * H];
__device__ __nv_bfloat16 g_W2pl[(size_t)N2 * H];
__device__ float g_Mtmp[(size_t)H * H];
__device__ float g_T2i[(size_t)1536 * H];
__device__ float g_T2h[(size_t)1536 * H];
__device__ float g_bbig[N2];
__device__ float g_bsum[N1];
__device__ float g_cx[B * H];
__device__ __nv_bfloat16 g_hx_h[B * H], g_hx_l[B * H];
__device__ __nv_bfloat16 g_h1_h[B * H], g_h1_l[B * H];
__device__ unsigned g_count = 0;
__device__ volatile unsigned g_sense = 0;

// ---------------- helpers ----------------
__device__ __forceinline__ float sigmoidf_(float x) { return 1.0f / (1.0f + expf(-x)); }

__device__ __forceinline__ void split2(float x, __nv_bfloat16& h, __nv_bfloat16& l) {
    h = __float2bfloat16_rn(x);
    l = __float2bfloat16_rn(x - __bfloat162float(h));
}

__device__ __forceinline__ uint32_t smem_u32(const void* p) {
    uint32_t a;
    asm("{ .reg .u64 t; cvta.to.shared.u64 t, %1; cvt.u32.u64 %0, t; }" : "=r"(a) : "l"(p));
    return a;
}

__device__ __forceinline__ void cpasync_cg(uint32_t dst, const void* src) {
    asm volatile("cp.async.cg.shared.global [%0], [%1], 16;" :: "r"(dst), "l"(src) : "memory");
}
__device__ __forceinline__ void cpasync_ca(uint32_t dst, const void* src) {
    asm volatile("cp.async.ca.shared.global [%0], [%1], 16;" :: "r"(dst), "l"(src) : "memory");
}
#define CP_COMMIT() asm volatile("cp.async.commit_group;" ::: "memory")
#define CP_WAIT1()  asm volatile("cp.async.wait_group 1;" ::: "memory")
#define CP_WAIT0()  asm volatile("cp.async.wait_group 0;" ::: "memory")

__device__ __forceinline__ void ldsm4(uint32_t r[4], uint32_t addr) {
    asm volatile("ldmatrix.sync.aligned.m8n8.x4.shared.b16 {%0,%1,%2,%3}, [%4];"
                 : "=r"(r[0]), "=r"(r[1]), "=r"(r[2]), "=r"(r[3]) : "r"(addr));
}

__device__ __forceinline__ void mma16816(float c[4], const uint32_t a[4],
                                         uint32_t b0, uint32_t b1) {
    asm volatile(
        "mma.sync.aligned.m16n8k16.row.col.f32.bf16.bf16.f32 "
        "{%0,%1,%2,%3}, {%4,%5,%6,%7}, {%8,%9}, {%0,%1,%2,%3};"
        : "+f"(c[0]), "+f"(c[1]), "+f"(c[2]), "+f"(c[3])
        : "r"(a[0]), "r"(a[1]), "r"(a[2]), "r"(a[3]), "r"(b0), "r"(b1));
}

__device__ __forceinline__ void st_cg_u16(__nv_bfloat16* p, __nv_bfloat16 v) {
    uint16_t u = __bfloat16_as_ushort(v);
    asm volatile("st.global.cg.u16 [%0], %1;" :: "l"(p), "h"(u) : "memory");
}

// ---- loaders: A part (RA rows), B part (128 rows), 64 halves per row, hi+lo ----
template <int RA>
__device__ __forceinline__ void load_A(
    uint32_t sbuf,
    const __nv_bfloat16* __restrict__ Ah, const __nv_bfloat16* __restrict__ Al, int lda,
    int tid)
{
    #pragma unroll
    for (int i = 0; i < RA / 32; i++) {
        int seg = tid + i * 256;
        int row = seg >> 3, q = seg & 7;
        uint32_t d = (uint32_t)(row * RSTR + q * 16);
        cpasync_cg(sbuf + OFF_AH + d, Ah + (size_t)row * lda + q * 8);
        cpasync_cg(sbuf + OFF_AL + d, Al + (size_t)row * lda + q * 8);
    }
}
__device__ __forceinline__ void load_B(
    uint32_t sbuf,
    const __nv_bfloat16* __restrict__ Bh, const __nv_bfloat16* __restrict__ Bl, int ldb,
    int tid)
{
    #pragma unroll
    for (int i = 0; i < 4; i++) {
        int seg = tid + i * 256;
        int row = seg >> 3, q = seg & 7;
        uint32_t d = (uint32_t)(row * RSTR + q * 16);
        cpasync_ca(sbuf + OFF_BH + d, Bh + (size_t)row * ldb + q * 8);
        cpasync_ca(sbuf + OFF_BL + d, Bl + (size_t)row * ldb + q * 8);
    }
}

// ---- warp MMA over one K=64 chunk, 3 INDEPENDENT accumulator sets ----
template <int NB8>
__device__ __forceinline__ void chunk_mma3(uint32_t sbuf, int mbase, int nbase, int lane,
                                           float chh[2][NB8][4], float clh[2][NB8][4],
                                           float chl[2][NB8][4])
{
    int lr = lane & 15, ls = lane >> 4;
    uint32_t aoff = (uint32_t)(lr * RSTR + ls * 16);
    uint32_t aAh = sbuf + OFF_AH + (uint32_t)mbase * RSTR + aoff;
    uint32_t aAl = sbuf + OFF_AL + (uint32_t)mbase * RSTR + aoff;
    uint32_t aBh = sbuf + OFF_BH + (uint32_t)nbase * RSTR + aoff;
    uint32_t aBl = sbuf + OFF_BL + (uint32_t)nbase * RSTR + aoff;
    #pragma unroll
    for (int kk = 0; kk < 4; kk++) {
        uint32_t ko = kk * 32;
        uint32_t Ah[2][4], Al[2][4], Bh[NB8 / 2][4], Bl[NB8 / 2][4];
        ldsm4(Ah[0], aAh + ko);
        ldsm4(Ah[1], aAh + 16 * RSTR + ko);
        ldsm4(Al[0], aAl + ko);
        ldsm4(Al[1], aAl + 16 * RSTR + ko);
        #pragma unroll
        for (int j = 0; j < NB8 / 2; j++) {
            ldsm4(Bh[j], aBh + j * 16 * RSTR + ko);
            ldsm4(Bl[j], aBl + j * 16 * RSTR + ko);
        }
        // set 1: Ah*Bh
        #pragma unroll
        for (int mi = 0; mi < 2; mi++)
            #pragma unroll
            for (int j = 0; j < NB8 / 2; j++) {
                mma16816(chh[mi][2 * j],     Ah[mi], Bh[j][0], Bh[j][2]);
                mma16816(chh[mi][2 * j + 1], Ah[mi], Bh[j][1], Bh[j][3]);
            }
        // set 2: Al*Bh
        #pragma unroll
        for (int mi = 0; mi < 2; mi++)
            #pragma unroll
            for (int j = 0; j < NB8 / 2; j++) {
                mma16816(clh[mi][2 * j],     Al[mi], Bh[j][0], Bh[j][2]);
                mma16816(clh[mi][2 * j + 1], Al[mi], Bh[j][1], Bh[j][3]);
            }
        // set 3: Ah*Bl
        #pragma unroll
        for (int mi = 0; mi < 2; mi++)
            #pragma unroll
            for (int j = 0; j < NB8 / 2; j++) {
                mma16816(chl[mi][2 * j],     Ah[mi], Bl[j][0], Bl[j][2]);
                mma16816(chl[mi][2 * j + 1], Ah[mi], Bl[j][1], Bl[j][3]);
            }
    }
}

// ---- C fragments (3 sets summed) -> smem float staging (stride 132 floats) ----
template <int NB8>
__device__ __forceinline__ void store_C3(float* sC, int mbase, int nbase, int lane,
                                         float chh[2][NB8][4], float clh[2][NB8][4],
                                         float chl[2][NB8][4])
{
    int tq = lane >> 2, tr = lane & 3;
    #pragma unroll
    for (int mi = 0; mi < 2; mi++) {
        #pragma unroll
        for (int ni = 0; ni < NB8; ni++) {
            float v0 = chh[mi][ni][0] + clh[mi][ni][0] + chl[mi][ni][0];
            float v1 = chh[mi][ni][1] + clh[mi][ni][1] + chl[mi][ni][1];
            float v2 = chh[mi][ni][2] + clh[mi][ni][2] + chl[mi][ni][2];
            float v3 = chh[mi][ni][3] + clh[mi][ni][3] + chl[mi][ni][3];
            int r = mbase + mi * 16 + tq;
            int col = nbase + ni * 8 + tr * 2;
            *(float2*)&sC[(size_t)r * 132 + col] = make_float2(v0, v1);
            *(float2*)&sC[(size_t)(r + 8) * 132 + col] = make_float2(v2, v3);
        }
    }
}

// ---------------- grid barrier ----------------
__device__ __forceinline__ void grid_barrier(unsigned& gen) {
    __syncthreads();
    if (threadIdx.x == 0) {
        __threadfence();
        if (atomicAdd(&g_count, 1u) == GB_N - 1) {
            g_count = 0;
            __threadfence();
            g_sense = gen + 1;
        } else {
            while (g_sense == gen) { }
            __threadfence();
        }
        gen = gen + 1;
    }
    __syncthreads();
}

// ---------------- precompute kernels ----------------
__global__ void k_init() {
    int i = blockIdx.x * blockDim.x + threadIdx.x;
    if (i < B * H) {
        g_hx_h[i] = __ushort_as_bfloat16(0);
        g_hx_l[i] = __ushort_as_bfloat16(0);
    }
}

__global__ void k_pack_inputs(const float* __restrict__ src) {
    size_t n = (size_t)T_STEPS * B * D;
    for (size_t i = blockIdx.x * (size_t)blockDim.x + threadIdx.x; i < n;
         i += (size_t)gridDim.x * blockDim.x) {
        __nv_bfloat16 h, l;
        split2(src[i], h, l);
        g_in_h[i] = h; g_in_l[i] = l;
    }
}

__global__ void k_pack_w1(const float* __restrict__ Wih, const float* __restrict__ Whh) {
    size_t n = (size_t)N1 * KFULL;
    for (size_t i = blockIdx.x * (size_t)blockDim.x + threadIdx.x; i < n;
         i += (size_t)gridDim.x * blockDim.x) {
        int p = (int)(i / KFULL), k = (int)(i % KFULL);
        int hh = p >> 2, g = p & 3;
        int j = g * H + hh;
        float v = Wih[(size_t)j * KFULL + k];
        if (k >= D) v += Whh[(size_t)j * H + (k - D)];
        __nv_bfloat16 h, l;
        split2(v, h, l);
        g_W1h[i] = h; g_W1l[i] = l;
    }
}

__global__ __launch_bounds__(256) void gemm_nt(
    const float* __restrict__ A, const float* __restrict__ Bm, float* __restrict__ C,
    int K, int lda, int ldb, int ldc)
{
    __shared__ float sA[32][33];
    __shared__ float sB[32][33];
    int t = threadIdx.x;
    int i0 = blockIdx.x * 32, j0 = blockIdx.y * 32;
    int tx = t & 15, ty = t >> 4;
    float a00 = 0.f, a01 = 0.f, a10 = 0.f, a11 = 0.f;
    for (int l0 = 0; l0 < K; l0 += 32) {
        #pragma unroll
        for (int i = 0; i < 4; i++) {
            int e = t + i * 256; int r = e >> 5, cc = e & 31;
            sA[r][cc] = A[(size_t)(i0 + r) * lda + l0 + cc];
            sB[r][cc] = Bm[(size_t)(j0 + r) * ldb + l0 + cc];
        }
        __syncthreads();
        #pragma unroll
        for (int ll = 0; ll < 32; ll++) {
            float x0 = sA[ty * 2][ll], x1 = sA[ty * 2 + 1][ll];
            float y0 = sB[tx * 2][ll], y1 = sB[tx * 2 + 1][ll];
            a00 += x0 * y0; a01 += x0 * y1; a10 += x1 * y0; a11 += x1 * y1;
        }
        __syncthreads();
    }
    C[(size_t)(i0 + ty * 2) * ldc + j0 + tx * 2]         = a00;
    C[(size_t)(i0 + ty * 2) * ldc + j0 + tx * 2 + 1]     = a01;
    C[(size_t)(i0 + ty * 2 + 1) * ldc + j0 + tx * 2]     = a10;
    C[(size_t)(i0 + ty * 2 + 1) * ldc + j0 + tx * 2 + 1] = a11;
}

__global__ void k_pack_w2() {
    size_t n = (size_t)N2 * H;
    for (size_t i = blockIdx.x * (size_t)blockDim.x + threadIdx.x; i < n;
         i += (size_t)gridDim.x * blockDim.x) {
        int p = (int)(i >> 9), k = (int)(i & 511);
        int hh = p >> 3, blk = p & 7;
        float v;
        if (blk < 3)       v = g_T2i[(size_t)(blk * H + hh) * H + k];
        else if (blk < 6)  v = g_T2h[(size_t)((blk - 3) * H + hh) * H + k];
        else if (blk == 6) v = g_Mtmp[(size_t)k * H + hh];
        else               v = 0.0f;
        __nv_bfloat16 h, l;
        split2(v, h, l);
        g_W2ph[i] = h; g_W2pl[i] = l;
    }
}

__global__ void k_bbig_perm(const float* __restrict__ feb,
                            const float* __restrict__ gWih, const float* __restrict__ gWhh,
                            const float* __restrict__ gbih, const float* __restrict__ gbhh) {
    int p = blockIdx.x * blockDim.x + threadIdx.x;
    if (p >= N2) return;
    int hh = p >> 3, blk = p & 7;
    float s = 0.0f;
    if (blk < 3) {
        int j = blk * H + hh;
        const float* w = gWih + (size_t)j * H;
        s = gbih[j];
        for (int k = 0; k < H; k++) s += feb[k] * w[k];
    } else if (blk < 6) {
        int j = (blk - 3) * H + hh;
        const float* w = gWhh + (size_t)j * H;
        s = gbhh[j];
        for (int k = 0; k < H; k++) s += feb[k] * w[k];
    } else if (blk == 6) {
        s = feb[hh];
    }
    g_bbig[p] = s;
}

__global__ void k_bsum_perm(const float* __restrict__ bih, const float* __restrict__ bhh) {
    int p = blockIdx.x * blockDim.x + threadIdx.x;
    if (p < N1) {
        int hh = p >> 2, g = p & 3;
        int j = g * H + hh;
        g_bsum[p] = bih[j] + bhh[j];
    }
}

// ---------------- persistent recurrence ----------------
__global__ void __launch_bounds__(256, 1) k_recur(float* __restrict__ out) {
    extern __shared__ char smraw[];
    uint32_t sb0 = (smem_u32(smraw) + 127u) & ~127u;
    char* smbase = smraw + (sb0 - smem_u32(smraw));
    uint32_t sbuf[2] = { sb0, sb0 + BUF_BYTES };
    float* sC = (float*)(smbase + 2 * BUF_BYTES);   // dedicated staging

    int tid = threadIdx.x, lane = tid & 31, w = tid >> 5, bid = blockIdx.x;

    // stage1 mapping: tile 32(M) x 128(N); warp tile 32x16 (NB8=2)
    int mt1 = bid >> 4, nt1 = bid & 15;
    int m1row0 = mt1 * 32;
    int nb1 = w * 16;
    const __nv_bfloat16* W1hB = g_W1h + (size_t)(nt1 * 128) * KFULL;
    const __nv_bfloat16* W1lB = g_W1l + (size_t)(nt1 * 128) * KFULL;

    // stage2 mapping: tile 64 x 128; warp tile 32x32 (NB8=4)
    int mt2 = bid >> 5, nt2 = bid & 31;
    int m2row0 = mt2 * 64;
    int mb2 = (w >> 2) * 32, nb2 = (w & 3) * 32;
    const __nv_bfloat16* W2hB = g_W2ph + (size_t)(nt2 * 128) * H;
    const __nv_bfloat16* W2lB = g_W2pl + (size_t)(nt2 * 128) * H;

    float cxr[4] = {0.f, 0.f, 0.f, 0.f};
    unsigned gen = 0;
    if (tid == 0) gen = g_sense;     // survive graph replays

    // initial prefetch: stage1 chunk 0 (pure x part + W1)
    load_A<32>(sbuf[0], g_in_h + (size_t)m1row0 * D, g_in_l + (size_t)m1row0 * D, D, tid);
    load_B(sbuf[0], W1hB, W1lB, KFULL, tid);
    CP_COMMIT();

    for (int t = 0; t < T_STEPS; t++) {
        // ================= stage 1: gates = [x_t | hx] @ W1^T (K=768) =================
        {
            auto a1 = [&](int kc, const __nv_bfloat16*& ph, const __nv_bfloat16*& pl, int& lda) {
                if (kc < 4) {
                    ph = g_in_h + ((size_t)t * B + m1row0) * D + kc * 64;
                    pl = g_in_l + ((size_t)t * B + m1row0) * D + kc * 64;
                    lda = D;
                } else {
                    ph = g_hx_h + (size_t)m1row0 * H + (kc * 64 - D);
                    pl = g_hx_l + (size_t)m1row0 * H + (kc * 64 - D);
                    lda = H;
                }
            };
            float chh[2][2][4], clh[2][2][4], chl[2][2][4];
            #pragma unroll
            for (int a = 0; a < 2; a++)
                #pragma unroll
                for (int b2 = 0; b2 < 2; b2++)
                    #pragma unroll
                    for (int q = 0; q < 4; q++) {
                        chh[a][b2][q] = 0.f; clh[a][b2][q] = 0.f; chl[a][b2][q] = 0.f;
                    }

            for (int kc = 0; kc < 12; kc++) {
                if (kc < 11) {
                    const __nv_bfloat16 *ph, *pl; int lda; a1(kc + 1, ph, pl, lda);
                    load_A<32>(sbuf[(kc + 1) & 1], ph, pl, lda, tid);
                    load_B(sbuf[(kc + 1) & 1],
                           W1hB + (kc + 1) * 64, W1lB + (kc + 1) * 64, KFULL, tid);
                    CP_COMMIT(); CP_WAIT1();
                } else {
                    CP_WAIT0();
                }
                __syncthreads();
                chunk_mma3<2>(sbuf[kc & 1], 0, nb1, lane, chh, clh, chl);
                __syncthreads();
            }
            store_C3<2>(sC, 0, nb1, lane, chh, clh, chl);
        }
        __syncthreads();
        // EW1: LSTM elementwise (cols = 4h+g), cx in registers
        #pragma unroll
        for (int i = 0; i < 4; i++) {
            int cid = tid + i * 256;
            int r = cid >> 5, hl = cid & 31;
            int pb = nt1 * 128 + hl * 4;
            float gi = sC[(size_t)r * 132 + hl * 4 + 0] + __ldg(&g_bsum[pb + 0]);
            float gf = sC[(size_t)r * 132 + hl * 4 + 1] + __ldg(&g_bsum[pb + 1]);
            float gg = sC[(size_t)r * 132 + hl * 4 + 2] + __ldg(&g_bsum[pb + 2]);
            float go = sC[(size_t)r * 132 + hl * 4 + 3] + __ldg(&g_bsum[pb + 3]);
            float iv = sigmoidf_(gi);
            float fv = sigmoidf_(gf);
            float gv = tanhf(gg);
            float ov = sigmoidf_(go);
            float cn = fv * cxr[i] + iv * gv;
            cxr[i] = cn;
            float h1v = ov * tanhf(cn);
            int b = m1row0 + r;
            int hg = nt1 * 32 + hl;
            __nv_bfloat16 hh, ll;
            split2(h1v, hh, ll);
            st_cg_u16(&g_h1_h[(size_t)b * H + hg], hh);
            st_cg_u16(&g_h1_l[(size_t)b * H + hg], ll);
            if (t == T_STEPS - 1) g_cx[(size_t)b * H + hg] = cn;
        }
        // prefetch stage2 chunk0 WEIGHTS (h1-independent) before the barrier
        load_B(sbuf[0], W2hB, W2lB, H, tid);
        CP_COMMIT();
        grid_barrier(gen);
        // now h1 is globally visible: fetch stage2 chunk0 A
        load_A<64>(sbuf[0], g_h1_h + (size_t)m2row0 * H, g_h1_l + (size_t)m2row0 * H, H, tid);
        CP_COMMIT();

        // ================= stage 2: Z = h1 @ W2^T (K=512) =================
        {
            float chh[2][4][4], clh[2][4][4], chl[2][4][4];
            #pragma unroll
            for (int a = 0; a < 2; a++)
                #pragma unroll
                for (int b2 = 0; b2 < 4; b2++)
                    #pragma unroll
                    for (int q = 0; q < 4; q++) {
                        chh[a][b2][q] = 0.f; clh[a][b2][q] = 0.f; chl[a][b2][q] = 0.f;
                    }

            for (int kc = 0; kc < 8; kc++) {
                if (kc < 7) {
                    load_A<64>(sbuf[(kc + 1) & 1],
                               g_h1_h + (size_t)m2row0 * H + (kc + 1) * 64,
                               g_h1_l + (size_t)m2row0 * H + (kc + 1) * 64, H, tid);
                    load_B(sbuf[(kc + 1) & 1],
                           W2hB + (kc + 1) * 64, W2lB + (kc + 1) * 64, H, tid);
                    CP_COMMIT(); CP_WAIT1();
                } else {
                    CP_WAIT0();
                }
                __syncthreads();
                chunk_mma3<4>(sbuf[kc & 1], mb2, nb2, lane, chh, clh, chl);
                __syncthreads();
            }
            store_C3<4>(sC, mb2, nb2, lane, chh, clh, chl);
        }
        __syncthreads();
        // EW2: GRU elementwise (cols = 8h+blk, blk 0..6)
        #pragma unroll
        for (int i = 0; i < 4; i++) {
            int cid = tid + i * 256;
            int r = cid >> 4, hl = cid & 15;
            int pb = nt2 * 128 + hl * 8;
            const float* cc = &sC[(size_t)r * 132 + hl * 8];
            float ir  = cc[0] + __ldg(&g_bbig[pb + 0]);
            float izv = cc[1] + __ldg(&g_bbig[pb + 1]);
            float inn = cc[2] + __ldg(&g_bbig[pb + 2]);
            float hr  = cc[3] + __ldg(&g_bbig[pb + 3]);
            float hz  = cc[4] + __ldg(&g_bbig[pb + 4]);
            float hn  = cc[5] + __ldg(&g_bbig[pb + 5]);
            float h3  = cc[6] + __ldg(&g_bbig[pb + 6]);
            float rv = sigmoidf_(ir + hr);
            float zz = sigmoidf_(izv + hz);
            float nn = tanhf(inn + rv * hn);
            float hnew = (1.0f - zz) * nn + zz * h3;
            int b = m2row0 + r;
            int hg = nt2 * 16 + hl;
            out[((size_t)t * B + b) * H + hg] = hnew;
            __nv_bfloat16 hh, ll;
            split2(hnew, hh, ll);
            st_cg_u16(&g_hx_h[(size_t)b * H + hg], hh);
            st_cg_u16(&g_hx_l[(size_t)b * H + hg], ll);
        }
        // prefetch NEXT step's stage1 chunk0 (pure x + static W1) before the barrier
        {
            int tn = (t + 1 < T_STEPS) ? t + 1 : t;
            load_A<32>(sbuf[0],
                       g_in_h + ((size_t)tn * B + m1row0) * D,
                       g_in_l + ((size_t)tn * B + m1row0) * D, D, tid);
            load_B(sbuf[0], W1hB, W1lB, KFULL, tid);
            CP_COMMIT();
        }
        grid_barrier(gen);
    }
}

// ---------------- finalize ----------------
__global__ void k_finalize(float* __restrict__ out) {
    int i = blockIdx.x * blockDim.x + threadIdx.x;
    if (i < B * H) {
        out[(size_t)T_STEPS * B * H + i] = out[(size_t)(T_STEPS - 1) * B * H + i];
        out[(size_t)T_STEPS * B * H + B * H + i] = g_cx[i];
    }
}

// ---------------- host ----------------
extern "C" void kernel_launch(void* const* d_in, const int* in_sizes, int n_in,
                              void* d_out, int out_size) {
    (void)in_sizes; (void)n_in; (void)out_size;
    const float* inputs   = (const float*)d_in[0];
    const float* lstm_Wih = (const float*)d_in[1];
    const float* lstm_Whh = (const float*)d_in[2];
    const float* lstm_bih = (const float*)d_in[3];
    const float* lstm_bhh = (const float*)d_in[4];
    const float* phase    = (const float*)d_in[5];
    const float* fe_W     = (const float*)d_in[6];
    const float* fe_b     = (const float*)d_in[7];
    const float* gru_Wih  = (const float*)d_in[8];
    const float* gru_Whh  = (const float*)d_in[9];
    const float* gru_bih  = (const float*)d_in[10];
    const float* gru_bhh  = (const float*)d_in[11];
    float* out = (float*)d_out;

    float *pM, *pT2i, *pT2h;
    cudaGetSymbolAddress((void**)&pM, g_Mtmp);
    cudaGetSymbolAddress((void**)&pT2i, g_T2i);
    cudaGetSymbolAddress((void**)&pT2h, g_T2h);

    cudaFuncSetAttribute(k_recur, cudaFuncAttributeMaxDynamicSharedMemorySize, DYN_SMEM);

    k_init<<<(B * H + 255) / 256, 256>>>();
    k_pack_inputs<<<2048, 256>>>(inputs);
    k_pack_w1<<<2048, 256>>>(lstm_Wih, lstm_Whh);

    gemm_nt<<<dim3(H / 32, H / 32), 256>>>(phase, fe_W, pM, H, H, H, H);
    gemm_nt<<<dim3(1536 / 32, H / 32), 256>>>(gru_Wih, pM, pT2i, H, H, H, H);
    gemm_nt<<<dim3(1536 / 32, H / 32), 256>>>(gru_Whh, pM, pT2h, H, H, H, H);

    k_pack_w2<<<4096, 256>>>();
    k_bbig_perm<<<(N2 + 255) / 256, 256>>>(fe_b, gru_Wih, gru_Whh, gru_bih, gru_bhh);
    k_bsum_perm<<<(N1 + 255) / 256, 256>>>(lstm_bih, lstm_bhh);

    k_recur<<<GB_N, 256, DYN_SMEM>>>(out);

    k_finalize<<<(B * H + 255) / 256, 256>>>(out);
}